// round 16
// baseline (speedup 1.0000x reference)
#include <cuda_runtime.h>
#include <cstdint>
#include <cstddef>

// Problem constants
#define T_STEPS 1024
#define BB      64          // B
#define DD      256         // D
#define HH      512         // H
#define LL      64          // L
#define ROWS    256         // S*B
#define NC3     1536        // 3*H
#define TWO_L   128

#define NCTA    128         // persistent CTAs: 4 row-groups x 32 col-groups
#define BLK     512

#define LOG2PI_F 1.8378770664093453f

typedef unsigned long long u64;

// ---------------- packed f32x2 helpers (sm_100+) ---------------------------------
__device__ __forceinline__ u64 pack2(float lo, float hi) {
    u64 r;
    asm("mov.b64 %0, {%1, %2};" : "=l"(r) : "r"(__float_as_uint(lo)), "r"(__float_as_uint(hi)));
    return r;
}
__device__ __forceinline__ u64 bcast2(float v) {
    u64 r; unsigned u = __float_as_uint(v);
    asm("mov.b64 %0, {%1, %1};" : "=l"(r) : "r"(u));
    return r;
}
__device__ __forceinline__ void unpack2(u64 p, float& lo, float& hi) {
    unsigned a, b;
    asm("mov.b64 {%0, %1}, %2;" : "=r"(a), "=r"(b) : "l"(p));
    lo = __uint_as_float(a); hi = __uint_as_float(b);
}
__device__ __forceinline__ void fma2(u64& d, u64 a, u64 b) {
    asm("fma.rn.f32x2 %0, %1, %2, %3;" : "=l"(d) : "l"(a), "l"(b), "l"(d));
}

// ---------------- cp.async (L2 path, avoids stale L1) ----------------------------
__device__ __forceinline__ void cp16(float* dst_s, const float* src_g) {
    unsigned d = (unsigned)__cvta_generic_to_shared(dst_s);
    asm volatile("cp.async.cg.shared.global [%0], [%1], 16;" :: "r"(d), "l"(src_g));
}
#define CP_COMMIT() asm volatile("cp.async.commit_group;")
#define CP_WAIT2()  asm volatile("cp.async.wait_group 2;")
#define CP_WAIT1()  asm volatile("cp.async.wait_group 1;")
#define CP_WAIT0()  asm volatile("cp.async.wait_group 0;")

// ---------------- device global scratch ------------------------------------------
__device__ float d_XG[(size_t)T_STEPS * BB * NC3];   // x@Wx[:D] + b  (402 MB)
__device__ float d_hT[HH * ROWS];                    // h transposed  [k][row]
__device__ float d_rhT[HH * ROWS];                   // r*h transposed
__device__ float d_zT[LL * ROWS];                    // z transposed  [l][row]
__device__ float d_red[ROWS * 32 * 2];               // ent/lp partials [row][cg][2]
__device__ unsigned g_bar_count;
__device__ unsigned g_bar_gen;

// ---------------- grid-wide barrier (all CTAs resident in one wave) --------------
__device__ __forceinline__ void grid_barrier(unsigned target) {
    __syncthreads();
    if (threadIdx.x == 0) {
        __threadfence();
        unsigned prev = atomicAdd(&g_bar_count, 1u);
        if (prev == NCTA - 1) {
            g_bar_count = 0;
            __threadfence();
            atomicExch(&g_bar_gen, target);
        } else {
            unsigned g;
            do {
                asm volatile("ld.acquire.gpu.u32 %0, [%1];" : "=r"(g) : "l"(&g_bar_gen) : "memory");
                if (g >= target) break;
                __nanosleep(32);
            } while (1);
        }
    }
    __syncthreads();
}

// ---------------- init (split for ncu slot alignment) ----------------------------
__global__ void init_a() {
    int i = blockIdx.x * blockDim.x + threadIdx.x;
    int n = gridDim.x * blockDim.x;
    if (i == 0) { g_bar_count = 0; g_bar_gen = 0; }
    for (int k = i; k < HH * ROWS / 2; k += n) d_hT[k] = 0.0f;
}
__global__ void init_b() {
    int i = blockIdx.x * blockDim.x + threadIdx.x;
    int n = gridDim.x * blockDim.x;
    for (int k = i; k < HH * ROWS / 2; k += n) d_hT[HH * ROWS / 2 + k] = 0.0f;
}
__global__ void init_c() {
    int i = blockIdx.x * blockDim.x + threadIdx.x;
    int n = gridDim.x * blockDim.x;
    for (int k = i; k < LL * ROWS; k += n) d_zT[k] = 0.0f;
}
__global__ void init_d() {
    int i = blockIdx.x * blockDim.x + threadIdx.x;
    int n = gridDim.x * blockDim.x;
    for (int k = i; k < HH * ROWS; k += n) d_rhT[k] = 0.0f;
}

// ---------------- XG precompute: XG[t*64+b][n] = x[b,t,:]@Wx[:D,n] + bias[n] -----
#define ABM 64
#define ABN 64
#define ABK 16
__global__ void __launch_bounds__(256)
xg_kernel(const float* __restrict__ inp,   // (B,T,D)
          const float* __restrict__ Wx,    // (D+L, 3H)
          const float* __restrict__ bias)  // (3H,)
{
    __shared__ __align__(16) float As[ABK][ABM];
    __shared__ __align__(16) float Bs[ABK][ABN];
    const int tid = threadIdx.x;
    const int m0 = blockIdx.y * ABM;
    const int n0 = blockIdx.x * ABN;
    const int tx = tid & 15;
    const int ty = tid >> 4;

    float acc[4][4];
#pragma unroll
    for (int i = 0; i < 4; i++)
#pragma unroll
        for (int j = 0; j < 4; j++) acc[i][j] = 0.0f;

    for (int k0 = 0; k0 < DD; k0 += ABK) {
#pragma unroll
        for (int i = 0; i < 4; i++) {
            int idx = tid + i * 256;
            int m  = idx >> 4, kk = idx & 15;
            int mg = m0 + m;
            int b  = mg & 63;
            int t  = mg >> 6;
            As[kk][m] = inp[((size_t)b * T_STEPS + t) * DD + k0 + kk];
            int kk2 = idx >> 6, nn = idx & 63;
            Bs[kk2][nn] = Wx[(size_t)(k0 + kk2) * NC3 + n0 + nn];
        }
        __syncthreads();
#pragma unroll
        for (int kk = 0; kk < ABK; kk++) {
            float4 a4 = *(const float4*)&As[kk][ty * 4];
            float4 b4 = *(const float4*)&Bs[kk][tx * 4];
            acc[0][0] = fmaf(a4.x, b4.x, acc[0][0]); acc[0][1] = fmaf(a4.x, b4.y, acc[0][1]);
            acc[0][2] = fmaf(a4.x, b4.z, acc[0][2]); acc[0][3] = fmaf(a4.x, b4.w, acc[0][3]);
            acc[1][0] = fmaf(a4.y, b4.x, acc[1][0]); acc[1][1] = fmaf(a4.y, b4.y, acc[1][1]);
            acc[1][2] = fmaf(a4.y, b4.z, acc[1][2]); acc[1][3] = fmaf(a4.y, b4.w, acc[1][3]);
            acc[2][0] = fmaf(a4.z, b4.x, acc[2][0]); acc[2][1] = fmaf(a4.z, b4.y, acc[2][1]);
            acc[2][2] = fmaf(a4.z, b4.z, acc[2][2]); acc[2][3] = fmaf(a4.z, b4.w, acc[2][3]);
            acc[3][0] = fmaf(a4.w, b4.x, acc[3][0]); acc[3][1] = fmaf(a4.w, b4.y, acc[3][1]);
            acc[3][2] = fmaf(a4.w, b4.z, acc[3][2]); acc[3][3] = fmaf(a4.w, b4.w, acc[3][3]);
        }
        __syncthreads();
    }
    float4 bb = *(const float4*)&bias[n0 + tx * 4];
#pragma unroll
    for (int i = 0; i < 4; i++) {
        int mg = m0 + ty * 4 + i;
        float4 o;
        o.x = acc[i][0] + bb.x; o.y = acc[i][1] + bb.y;
        o.z = acc[i][2] + bb.z; o.w = acc[i][3] + bb.w;
        *(float4*)&d_XG[(size_t)mg * NC3 + n0 + tx * 4] = o;
    }
}

// ---------------- persistent scan kernel -----------------------------------------
// SMEM (floats):
//   WhS   512*48  per k: [32 zr-interleaved: {z0,z1,r0,r1} x 8tc][16 n]
//   WxzS  64*48   same interleave
//   WdS   512*4   per k: {mu0,mu1,raw0,raw1}
//   XGS   64*48   plain z16|r16|n16
//   zS    64*64
//   H     3 x 64*64 chunk buffers
//   dpS   64*8, lsS 128, lpS 128
#define SM_WH    0
#define SM_WXZ   (SM_WH  + 512*48)
#define SM_WD    (SM_WXZ + 64*48)
#define SM_XG    (SM_WD  + 512*4)
#define SM_Z     (SM_XG  + 64*48)
#define SM_H     (SM_Z   + 64*64)
#define SM_DP    (SM_H   + 3*64*64)
#define SM_LS    (SM_DP  + 64*8)
#define SM_LP    (SM_LS  + 128)
#define SM_FLOATS (SM_LP + 128)
#define SMEM_BYTES (SM_FLOATS * 4)

__global__ void __launch_bounds__(BLK, 1)
scan_kernel(const float* __restrict__ noise,   // (T, S*B, L)
            const float* __restrict__ Wx,      // (D+L, 3H)
            const float* __restrict__ Wh,      // (H, 3H)
            const float* __restrict__ Wd,      // (H, 2L)
            const float* __restrict__ bd,      // (2L,)
            float* __restrict__ out)
{
    extern __shared__ float sm[];
    float* WhS  = sm + SM_WH;
    float* WxzS = sm + SM_WXZ;
    float* WdS  = sm + SM_WD;
    float* XGS  = sm + SM_XG;
    float* zS   = sm + SM_Z;
    float* dpS  = sm + SM_DP;
    float* lsS  = sm + SM_LS;
    float* lpS  = sm + SM_LP;

    const int tid = threadIdx.x;
    const int tc  = tid >> 6;            // 0..7
    const int rr  = tid & 63;            // local row 0..63
    const int cg  = blockIdx.x >> 2;     // col-group 0..31
    const int rg  = blockIdx.x & 3;      // row-group 0..3
    const int grow = rg * 64 + rr;       // global row
    const int jb  = cg * 16 + tc * 2;    // 2 hidden columns owned
    const int jbl = jb & 63;
    const int cjb = jb >> 6;
    const int dtc   = tc & 3;            // decoder slot: mu0,mu1,raw0,raw1
    const int dHalf = tc >> 2;           // which chunk-half this thread decodes
    const int dcol  = (dtc < 2) ? (cg * 2 + dtc) : (LL + cg * 2 + (dtc - 2));

    // ---- persistent weights (interleaved zr) ----
    for (int idx = tid; idx < HH * 48; idx += BLK) {
        int k = idx / 48, p = idx % 48;
        float v;
        if (p < 32) {
            int u = p >> 2, q = p & 3;
            int gate = q >> 1;
            v = Wh[(size_t)k * NC3 + gate * HH + cg * 16 + u * 2 + (q & 1)];
        } else {
            v = Wh[(size_t)k * NC3 + 2 * HH + cg * 16 + (p - 32)];
        }
        WhS[idx] = v;
    }
    for (int idx = tid; idx < LL * 48; idx += BLK) {
        int l = idx / 48, p = idx % 48;
        float v;
        if (p < 32) {
            int u = p >> 2, q = p & 3;
            int gate = q >> 1;
            v = Wx[(size_t)(DD + l) * NC3 + gate * HH + cg * 16 + u * 2 + (q & 1)];
        } else {
            v = Wx[(size_t)(DD + l) * NC3 + 2 * HH + cg * 16 + (p - 32)];
        }
        WxzS[idx] = v;
    }
    for (int idx = tid; idx < HH * 4; idx += BLK) {
        int k = idx >> 2, u = idx & 3;
        int c2 = (u < 2) ? (cg * 2 + u) : (LL + cg * 2 + (u - 2));
        WdS[idx] = Wd[(size_t)k * TWO_L + c2];
    }
    __syncthreads();

    const float bdv = (dHalf == 0) ? bd[dcol] : 0.0f;

    float* out_z   = out;
    float* out_ent = out + (size_t)ROWS * T_STEPS * LL;
    float* out_lp  = out_ent + (size_t)ROWS * T_STEPS;

    unsigned gen = 0;
    u64 az01 = 0, ar01 = 0, an01 = 0;
    float zg0 = 0, zg1 = 0;
    float h40 = 0, h41 = 0;

    for (int t = 0; t <= T_STEPS; t++) {
        const int tm1 = t - 1;
        // =============== P1: h-GEMM (z,r) + decoder + sampling =====================
        {
            if (t < T_STEPS) {
                const float* xg_t = d_XG + (size_t)t * BB * NC3;
#pragma unroll
                for (int it = 0; it < 2; it++) {
                    int idx4 = tid + it * BLK;
                    if (idx4 < 768) {
                        int b = idx4 / 12, uu = idx4 % 12;
                        cp16(&XGS[b * 48 + uu * 4],
                             &xg_t[(size_t)b * NC3 + (uu >> 2) * HH + cg * 16 + (uu & 3) * 4]);
                    }
                }
            }
#pragma unroll
            for (int it = 0; it < 2; it++) {
                int idx4 = tid + it * BLK;
                int kk = idx4 >> 4, q = idx4 & 15;
                cp16(&sm[SM_H + kk * 64 + q * 4], &d_hT[kk * ROWS + rg * 64 + q * 4]);
            }
            CP_COMMIT();
#pragma unroll
            for (int it = 0; it < 2; it++) {
                int idx4 = tid + it * BLK;
                int kk = idx4 >> 4, q = idx4 & 15;
                cp16(&sm[SM_H + 4096 + kk * 64 + q * 4], &d_hT[(64 + kk) * ROWS + rg * 64 + q * 4]);
            }
            CP_COMMIT();
#pragma unroll
            for (int it = 0; it < 2; it++) {
                int idx4 = tid + it * BLK;
                int kk = idx4 >> 4, q = idx4 & 15;
                cp16(&sm[SM_H + 8192 + kk * 64 + q * 4], &d_hT[(128 + kk) * ROWS + rg * 64 + q * 4]);
            }
            CP_COMMIT();
        }
        CP_WAIT2();
        __syncthreads();

        float accd = bdv;
        if (t < T_STEPS) {
            float2 xz = *(const float2*)&XGS[rr * 48 + tc * 2];
            float2 xr = *(const float2*)&XGS[rr * 48 + 16 + tc * 2];
            float2 xn = *(const float2*)&XGS[rr * 48 + 32 + tc * 2];
            az01 = pack2(xz.x, xz.y);
            ar01 = pack2(xr.x, xr.y);
            an01 = pack2(xn.x, xn.y);
        }

        for (int c = 0; c < 8; c++) {
            if (c > 0) {
                if (c < 6) CP_WAIT2(); else if (c == 6) CP_WAIT1(); else CP_WAIT0();
                __syncthreads();
            }
            const float* hB = sm + SM_H + (c % 3) * 4096;
            if (t < T_STEPS) {
                const float* wb = &WhS[(c * 64) * 48 + tc * 4];
                if ((c >> 2) == dHalf) {
                    const float* wdb = &WdS[(c * 64) * 4 + dtc];
#pragma unroll 8
                    for (int kk = 0; kk < 64; kk++) {
                        float hv = hB[kk * 64 + rr];
                        u64 h2 = bcast2(hv);
                        ulonglong2 wp = *(const ulonglong2*)(wb + kk * 48);
                        fma2(az01, h2, wp.x);
                        fma2(ar01, h2, wp.y);
                        accd = fmaf(hv, wdb[kk * 4], accd);
                    }
                } else {
#pragma unroll 8
                    for (int kk = 0; kk < 64; kk++) {
                        float hv = hB[kk * 64 + rr];
                        u64 h2 = bcast2(hv);
                        ulonglong2 wp = *(const ulonglong2*)(wb + kk * 48);
                        fma2(az01, h2, wp.x);
                        fma2(ar01, h2, wp.y);
                    }
                }
                if (c == cjb) {
                    h40 = hB[(jbl + 0) * 64 + rr];
                    h41 = hB[(jbl + 1) * 64 + rr];
                }
            } else {
                if ((c >> 2) == dHalf) {
                    const float* wdb = &WdS[(c * 64) * 4 + dtc];
#pragma unroll 8
                    for (int kk = 0; kk < 64; kk++)
                        accd = fmaf(hB[kk * 64 + rr], wdb[kk * 4], accd);
                }
            }
            __syncthreads();
            if (c + 3 < 8) {
                int cs = c + 3;
#pragma unroll
                for (int it = 0; it < 2; it++) {
                    int idx4 = tid + it * BLK;
                    int kk = idx4 >> 4, q = idx4 & 15;
                    cp16(&sm[SM_H + (cs % 3) * 4096 + kk * 64 + q * 4],
                         &d_hT[(cs * 64 + kk) * ROWS + rg * 64 + q * 4]);
                }
                CP_COMMIT();
            }
        }

        if (t >= 1) {
            dpS[rr * 8 + tc] = accd;
            __syncthreads();
            if (tc < 2) {
                float mu  = dpS[rr * 8 + tc]     + dpS[rr * 8 + tc + 4];
                float raw = dpS[rr * 8 + tc + 2] + dpS[rr * 8 + tc + 6];
                float sp  = fmaxf(raw, 0.0f) + log1pf(__expf(-fabsf(raw)));
                float sig = sp + 1e-4f;
                float lsig = logf(sig);
                int l = cg * 2 + tc;
                float eps = noise[((size_t)tm1 * ROWS + grow) * LL + l];
                float zv  = fmaf(sig, eps, mu);
                d_zT[l * ROWS + grow] = zv;
                out_z[((size_t)grow * T_STEPS + tm1) * LL + l] = zv;
                lsS[rr * 2 + tc] = lsig;
                lpS[rr * 2 + tc] = fmaf(-0.5f * eps, eps, -lsig);
            }
            __syncthreads();
            if (tc == 0) {
                float plsig = lsS[rr * 2] + lsS[rr * 2 + 1];
                float plp   = lpS[rr * 2] + lpS[rr * 2 + 1];
                d_red[(grow * 32 + cg) * 2 + 0] = plsig;
                d_red[(grow * 32 + cg) * 2 + 1] = plp;
            }
        }

        grid_barrier(++gen);

        // =============== P2: ent/lp reduction + z-part gates + rh ==================
        if (t < T_STEPS) {
#pragma unroll
            for (int it = 0; it < 2; it++) {
                int idx4 = tid + it * BLK;
                int l = idx4 >> 4, q = idx4 & 15;
                cp16(&zS[l * 64 + q * 4], &d_zT[l * ROWS + rg * 64 + q * 4]);
            }
            CP_COMMIT();
        }

        if (t >= 1) {
            int w = tid >> 5, lane = tid & 31;
            if (w < 8) {
                int row = blockIdx.x * 2 + (w >> 2);
                int sel = w & 3;
                if (sel < 2) {
                    float v;
                    asm volatile("ld.global.cg.f32 %0, [%1];" : "=f"(v)
                                 : "l"(&d_red[(row * 32 + lane) * 2 + sel]));
#pragma unroll
                    for (int off = 16; off; off >>= 1) v += __shfl_down_sync(0xffffffffu, v, off);
                    if (lane == 0) {
                        if (sel == 0)
                            out_ent[(size_t)row * T_STEPS + tm1] = 32.0f * (LOG2PI_F + 1.0f) + v;
                        else
                            out_lp[(size_t)row * T_STEPS + tm1] = v - 32.0f * LOG2PI_F;
                    }
                }
            }
        }

        if (t == T_STEPS) break;

        CP_WAIT0();
        __syncthreads();

#pragma unroll 4
        for (int l = 0; l < LL; l++) {
            u64 z2 = bcast2(zS[l * 64 + rr]);
            ulonglong2 wp = *(const ulonglong2*)&WxzS[l * 48 + tc * 4];
            u64 wn = *(const u64*)&WxzS[l * 48 + 32 + tc * 2];
            fma2(az01, z2, wp.x);
            fma2(ar01, z2, wp.y);
            fma2(an01, z2, wn);
        }
        {
            float az0, az1, ar0, ar1;
            unpack2(az01, az0, az1);
            unpack2(ar01, ar0, ar1);
            zg0 = __fdividef(1.0f, 1.0f + __expf(-az0));
            zg1 = __fdividef(1.0f, 1.0f + __expf(-az1));
            float rgt0 = __fdividef(1.0f, 1.0f + __expf(-ar0));
            float rgt1 = __fdividef(1.0f, 1.0f + __expf(-ar1));
            d_rhT[(jb + 0) * ROWS + grow] = rgt0 * h40;
            d_rhT[(jb + 1) * ROWS + grow] = rgt1 * h41;
        }

        grid_barrier(++gen);

        // =============== P3: rh-GEMM (n) + blend + h write =========================
#pragma unroll
        for (int pre = 0; pre < 3; pre++) {
#pragma unroll
            for (int it = 0; it < 2; it++) {
                int idx4 = tid + it * BLK;
                int kk = idx4 >> 4, q = idx4 & 15;
                cp16(&sm[SM_H + pre * 4096 + kk * 64 + q * 4],
                     &d_rhT[(pre * 64 + kk) * ROWS + rg * 64 + q * 4]);
            }
            CP_COMMIT();
        }
        CP_WAIT2();
        __syncthreads();

        for (int c = 0; c < 8; c++) {
            if (c > 0) {
                if (c < 6) CP_WAIT2(); else if (c == 6) CP_WAIT1(); else CP_WAIT0();
                __syncthreads();
            }
            const float* hB = sm + SM_H + (c % 3) * 4096;
            const float* wb = &WhS[(c * 64) * 48 + 32 + tc * 2];
#pragma unroll 8
            for (int kk = 0; kk < 64; kk++) {
                u64 r2 = bcast2(hB[kk * 64 + rr]);
                u64 wn = *(const u64*)(wb + kk * 48);
                fma2(an01, r2, wn);
            }
            __syncthreads();
            if (c + 3 < 8) {
                int cs = c + 3;
#pragma unroll
                for (int it = 0; it < 2; it++) {
                    int idx4 = tid + it * BLK;
                    int kk = idx4 >> 4, q = idx4 & 15;
                    cp16(&sm[SM_H + (cs % 3) * 4096 + kk * 64 + q * 4],
                         &d_rhT[(cs * 64 + kk) * ROWS + rg * 64 + q * 4]);
                }
                CP_COMMIT();
            }
        }

        {
            float an0, an1;
            unpack2(an01, an0, an1);
            float n0 = tanhf(an0), n1 = tanhf(an1);
            d_hT[(jb + 0) * ROWS + grow] = (1.0f - zg0) * n0 + zg0 * h40;
            d_hT[(jb + 1) * ROWS + grow] = (1.0f - zg1) * n1 + zg1 * h41;
        }

        grid_barrier(++gen);
    }
}

// ---------------- launch ---------------------------------------------------------
extern "C" void kernel_launch(void* const* d_in, const int* in_sizes, int n_in,
                              void* d_out, int out_size) {
    const float* inp   = (const float*)d_in[0];   // (B,T,D)
    const float* noise = (const float*)d_in[1];   // (T,S*B,L)
    const float* Wx    = (const float*)d_in[2];   // (D+L,3H)
    const float* Wh    = (const float*)d_in[3];   // (H,3H)
    const float* bias  = (const float*)d_in[4];   // (3H,)
    const float* Wd    = (const float*)d_in[5];   // (H,2L)
    const float* bd    = (const float*)d_in[6];   // (2L,)
    float* out = (float*)d_out;

    cudaFuncSetAttribute(scan_kernel, cudaFuncAttributeMaxDynamicSharedMemorySize, SMEM_BYTES);

    init_a<<<32, 256>>>();
    init_b<<<32, 256>>>();
    init_c<<<16, 256>>>();
    init_d<<<32, 256>>>();

    dim3 gA(NC3 / ABN, (T_STEPS * BB) / ABM);     // 24 x 1024
    xg_kernel<<<gA, 256>>>(inp, Wx, bias);

    scan_kernel<<<NCTA, BLK, SMEM_BYTES>>>(noise, Wx, Wh, Wd, bd, out);
}

// round 17
// speedup vs baseline: 1.7969x; 1.7969x over previous
#include <cuda_runtime.h>
#include <cstdint>
#include <cstddef>

// Problem constants
#define T_STEPS 1024
#define BB      64          // B
#define DD      256         // D
#define HH      512         // H
#define LL      64          // L
#define ROWS    256         // S*B
#define NC3     1536        // 3*H
#define TWO_L   128

#define NCTA    128         // persistent CTAs: 4 row-groups x 32 col-groups
#define BLK     256

#define LOG2PI_F 1.8378770664093453f

typedef unsigned long long u64;

// ---------------- packed f32x2 helpers (sm_100+) ---------------------------------
__device__ __forceinline__ u64 pack2(float lo, float hi) {
    u64 r;
    asm("mov.b64 %0, {%1, %2};" : "=l"(r) : "r"(__float_as_uint(lo)), "r"(__float_as_uint(hi)));
    return r;
}
__device__ __forceinline__ u64 bcast2(float v) {
    u64 r; unsigned u = __float_as_uint(v);
    asm("mov.b64 %0, {%1, %1};" : "=l"(r) : "r"(u));
    return r;
}
__device__ __forceinline__ void unpack2(u64 p, float& lo, float& hi) {
    unsigned a, b;
    asm("mov.b64 {%0, %1}, %2;" : "=r"(a), "=r"(b) : "l"(p));
    lo = __uint_as_float(a); hi = __uint_as_float(b);
}
__device__ __forceinline__ void fma2(u64& d, u64 a, u64 b) {
    asm("fma.rn.f32x2 %0, %1, %2, %3;" : "=l"(d) : "l"(a), "l"(b), "l"(d));
}

// ---------------- cp.async (L2 path, avoids stale L1) ----------------------------
__device__ __forceinline__ void cp16(float* dst_s, const float* src_g) {
    unsigned d = (unsigned)__cvta_generic_to_shared(dst_s);
    asm volatile("cp.async.cg.shared.global [%0], [%1], 16;" :: "r"(d), "l"(src_g));
}
#define CP_COMMIT() asm volatile("cp.async.commit_group;")
#define CP_WAIT2()  asm volatile("cp.async.wait_group 2;")
#define CP_WAIT0()  asm volatile("cp.async.wait_group 0;")

// ---------------- device global scratch ------------------------------------------
__device__ float d_XG[(size_t)T_STEPS * BB * NC3];   // x@Wx[:D] + b  (402 MB)
__device__ float d_hT[HH * ROWS];                    // h transposed  [k][row]
__device__ float d_rhT[HH * ROWS];                   // r*h transposed
__device__ float d_zT[LL * ROWS];                    // z transposed  [l][row]
__device__ float d_red[ROWS * 32 * 2];               // ent/lp partials [row][cg][2]
__device__ unsigned g_bar_count;
__device__ unsigned g_bar_gen;

// ---------------- grid-wide barrier (all CTAs resident in one wave) --------------
__device__ __forceinline__ void grid_barrier(unsigned target) {
    __syncthreads();
    if (threadIdx.x == 0) {
        __threadfence();
        unsigned prev = atomicAdd(&g_bar_count, 1u);
        if (prev == NCTA - 1) {
            g_bar_count = 0;
            __threadfence();
            atomicExch(&g_bar_gen, target);
        } else {
            unsigned g;
            do {
                asm volatile("ld.acquire.gpu.u32 %0, [%1];" : "=r"(g) : "l"(&g_bar_gen) : "memory");
                if (g >= target) break;
                __nanosleep(32);
            } while (1);
        }
    }
    __syncthreads();
}

// ---------------- init (split for ncu slot alignment) ----------------------------
__global__ void init_a() {
    int i = blockIdx.x * blockDim.x + threadIdx.x;
    int n = gridDim.x * blockDim.x;
    if (i == 0) { g_bar_count = 0; g_bar_gen = 0; }
    for (int k = i; k < HH * ROWS / 2; k += n) d_hT[k] = 0.0f;
}
__global__ void init_b() {
    int i = blockIdx.x * blockDim.x + threadIdx.x;
    int n = gridDim.x * blockDim.x;
    for (int k = i; k < HH * ROWS / 2; k += n) d_hT[HH * ROWS / 2 + k] = 0.0f;
}
__global__ void init_c() {
    int i = blockIdx.x * blockDim.x + threadIdx.x;
    int n = gridDim.x * blockDim.x;
    for (int k = i; k < LL * ROWS; k += n) d_zT[k] = 0.0f;
}
__global__ void init_d() {
    int i = blockIdx.x * blockDim.x + threadIdx.x;
    int n = gridDim.x * blockDim.x;
    for (int k = i; k < HH * ROWS; k += n) d_rhT[k] = 0.0f;
}

// ---------------- XG precompute: XG[t*64+b][n] = x[b,t,:]@Wx[:D,n] + bias[n] -----
#define ABM 64
#define ABN 64
#define ABK 16
__global__ void __launch_bounds__(256)
xg_kernel(const float* __restrict__ inp,   // (B,T,D)
          const float* __restrict__ Wx,    // (D+L, 3H)
          const float* __restrict__ bias)  // (3H,)
{
    __shared__ __align__(16) float As[ABK][ABM];
    __shared__ __align__(16) float Bs[ABK][ABN];
    const int tid = threadIdx.x;
    const int m0 = blockIdx.y * ABM;
    const int n0 = blockIdx.x * ABN;
    const int tx = tid & 15;
    const int ty = tid >> 4;

    float acc[4][4];
#pragma unroll
    for (int i = 0; i < 4; i++)
#pragma unroll
        for (int j = 0; j < 4; j++) acc[i][j] = 0.0f;

    for (int k0 = 0; k0 < DD; k0 += ABK) {
#pragma unroll
        for (int i = 0; i < 4; i++) {
            int idx = tid + i * 256;
            int m  = idx >> 4, kk = idx & 15;
            int mg = m0 + m;
            int b  = mg & 63;
            int t  = mg >> 6;
            As[kk][m] = inp[((size_t)b * T_STEPS + t) * DD + k0 + kk];
            int kk2 = idx >> 6, nn = idx & 63;
            Bs[kk2][nn] = Wx[(size_t)(k0 + kk2) * NC3 + n0 + nn];
        }
        __syncthreads();
#pragma unroll
        for (int kk = 0; kk < ABK; kk++) {
            float4 a4 = *(const float4*)&As[kk][ty * 4];
            float4 b4 = *(const float4*)&Bs[kk][tx * 4];
            acc[0][0] = fmaf(a4.x, b4.x, acc[0][0]); acc[0][1] = fmaf(a4.x, b4.y, acc[0][1]);
            acc[0][2] = fmaf(a4.x, b4.z, acc[0][2]); acc[0][3] = fmaf(a4.x, b4.w, acc[0][3]);
            acc[1][0] = fmaf(a4.y, b4.x, acc[1][0]); acc[1][1] = fmaf(a4.y, b4.y, acc[1][1]);
            acc[1][2] = fmaf(a4.y, b4.z, acc[1][2]); acc[1][3] = fmaf(a4.y, b4.w, acc[1][3]);
            acc[2][0] = fmaf(a4.z, b4.x, acc[2][0]); acc[2][1] = fmaf(a4.z, b4.y, acc[2][1]);
            acc[2][2] = fmaf(a4.z, b4.z, acc[2][2]); acc[2][3] = fmaf(a4.z, b4.w, acc[2][3]);
            acc[3][0] = fmaf(a4.w, b4.x, acc[3][0]); acc[3][1] = fmaf(a4.w, b4.y, acc[3][1]);
            acc[3][2] = fmaf(a4.w, b4.z, acc[3][2]); acc[3][3] = fmaf(a4.w, b4.w, acc[3][3]);
        }
        __syncthreads();
    }
    float4 bb = *(const float4*)&bias[n0 + tx * 4];
#pragma unroll
    for (int i = 0; i < 4; i++) {
        int mg = m0 + ty * 4 + i;
        float4 o;
        o.x = acc[i][0] + bb.x; o.y = acc[i][1] + bb.y;
        o.z = acc[i][2] + bb.z; o.w = acc[i][3] + bb.w;
        *(float4*)&d_XG[(size_t)mg * NC3 + n0 + tx * 4] = o;
    }
}

// ---------------- persistent scan kernel -----------------------------------------
// SMEM (floats):
//   WhS   512*48  per-CTA Wh slice (z16|r16|n16 cols of this col-group)
//   WxzS  64*48
//   WdS   512*4   per k: {mu0,mu1,raw0,raw1}
//   XGS   64*48
//   zS    64*64
//   H     4 x 64*64 chunk buffers (single-sync pipeline)
//   dpS   64*4, lsS 128, lpS 128
#define SM_WH    0
#define SM_WXZ   (SM_WH  + 512*48)
#define SM_WD    (SM_WXZ + 64*48)
#define SM_XG    (SM_WD  + 512*4)
#define SM_Z     (SM_XG  + 64*48)
#define SM_H     (SM_Z   + 64*64)
#define SM_DP    (SM_H   + 4*64*64)
#define SM_LS    (SM_DP  + 64*4)
#define SM_LP    (SM_LS  + 128)
#define SM_FLOATS (SM_LP + 128)
#define SMEM_BYTES (SM_FLOATS * 4)

__global__ void __launch_bounds__(BLK, 1)
scan_kernel(const float* __restrict__ noise,   // (T, S*B, L)
            const float* __restrict__ Wx,      // (D+L, 3H)
            const float* __restrict__ Wh,      // (H, 3H)
            const float* __restrict__ Wd,      // (H, 2L)
            const float* __restrict__ bd,      // (2L,)
            float* __restrict__ out)
{
    extern __shared__ float sm[];
    float* WhS  = sm + SM_WH;
    float* WxzS = sm + SM_WXZ;
    float* WdS  = sm + SM_WD;
    float* XGS  = sm + SM_XG;
    float* zS   = sm + SM_Z;
    float* dpS  = sm + SM_DP;
    float* lsS  = sm + SM_LS;
    float* lpS  = sm + SM_LP;

    const int tid = threadIdx.x;
    const int tc  = tid >> 6;            // 0..3
    const int rr  = tid & 63;            // local row 0..63
    const int cg  = blockIdx.x >> 2;     // col-group 0..31
    const int rg  = blockIdx.x & 3;      // row-group 0..3
    const int grow = rg * 64 + rr;       // global row
    const int jb  = cg * 16 + tc * 4;    // 4 hidden columns owned
    const int jbl = jb & 63;
    const int cjb = jb >> 6;
    const int dl  = cg * 2 + (tc & 1);   // decoder latent index
    const int dcol = (tc < 2) ? dl : (LL + dl);

    // ---- persistent weights ----
#pragma unroll
    for (int it = 0; it < 24; it++) {
        int idx4 = tid + it * 256;
        int k = idx4 / 12, uu = idx4 % 12;
        float4 v = *(const float4*)&Wh[(size_t)k * NC3 + (uu >> 2) * HH + cg * 16 + (uu & 3) * 4];
        *(float4*)&WhS[k * 48 + uu * 4] = v;
    }
#pragma unroll
    for (int it = 0; it < 3; it++) {
        int idx4 = tid + it * 256;
        int l = idx4 / 12, uu = idx4 % 12;
        float4 v = *(const float4*)&Wx[(size_t)(DD + l) * NC3 + (uu >> 2) * HH + cg * 16 + (uu & 3) * 4];
        *(float4*)&WxzS[l * 48 + uu * 4] = v;
    }
    for (int idx = tid; idx < HH * 4; idx += BLK) {
        int k = idx >> 2, u = idx & 3;
        int c2 = (u < 2) ? (cg * 2 + u) : (LL + cg * 2 + (u - 2));
        WdS[idx] = Wd[(size_t)k * TWO_L + c2];
    }
    __syncthreads();

    const float bdv = bd[dcol];

    float* out_z   = out;
    float* out_ent = out + (size_t)ROWS * T_STEPS * LL;
    float* out_lp  = out_ent + (size_t)ROWS * T_STEPS;

    unsigned gen = 0;
    u64 az01 = 0, az23 = 0, ar01 = 0, ar23 = 0, an01 = 0, an23 = 0;
    float zg0 = 0, zg1 = 0, zg2 = 0, zg3 = 0;
    float h40 = 0, h41 = 0, h42 = 0, h43 = 0;

    // ---- prefetch XG for t=0 ----
    {
        const float* xg_t = d_XG;
#pragma unroll
        for (int it = 0; it < 3; it++) {
            int idx4 = tid + it * 256;
            int b = idx4 / 12, uu = idx4 % 12;
            cp16(&XGS[b * 48 + uu * 4],
                 &xg_t[(size_t)b * NC3 + (uu >> 2) * HH + cg * 16 + (uu & 3) * 4]);
        }
        CP_COMMIT();
    }

    for (int t = 0; t <= T_STEPS; t++) {
        const int tm1 = t - 1;

        // =============== P1: h-GEMM (z,r) + decoder ================================
        // preload chunks 0,1 (XG group already pending from previous step / prologue)
#pragma unroll
        for (int pre = 0; pre < 2; pre++) {
#pragma unroll
            for (int it = 0; it < 4; it++) {
                int idx4 = tid + it * 256;
                int kk = idx4 >> 4, q = idx4 & 15;
                cp16(&sm[SM_H + pre * 4096 + kk * 64 + q * 4],
                     &d_hT[(pre * 64 + kk) * ROWS + rg * 64 + q * 4]);
            }
            CP_COMMIT();
        }

        float accd = bdv;
        for (int c = 0; c < 8; c++) {
            if (c + 2 < 8) {
                int cs = c + 2;
#pragma unroll
                for (int it = 0; it < 4; it++) {
                    int idx4 = tid + it * 256;
                    int kk = idx4 >> 4, q = idx4 & 15;
                    cp16(&sm[SM_H + (cs & 3) * 4096 + kk * 64 + q * 4],
                         &d_hT[(cs * 64 + kk) * ROWS + rg * 64 + q * 4]);
                }
            }
            CP_COMMIT();
            CP_WAIT2();
            __syncthreads();

            if (c == 0 && t < T_STEPS) {
                float4 xz = *(const float4*)&XGS[rr * 48 + tc * 4];
                float4 xr = *(const float4*)&XGS[rr * 48 + 16 + tc * 4];
                float4 xn = *(const float4*)&XGS[rr * 48 + 32 + tc * 4];
                az01 = pack2(xz.x, xz.y); az23 = pack2(xz.z, xz.w);
                ar01 = pack2(xr.x, xr.y); ar23 = pack2(xr.z, xr.w);
                an01 = pack2(xn.x, xn.y); an23 = pack2(xn.z, xn.w);
            }

            const float* hB = sm + SM_H + (c & 3) * 4096;
            if (t < T_STEPS) {
                const float* wb  = &WhS[(c * 64) * 48 + tc * 4];
                const float* wdb = &WdS[(c * 64) * 4 + tc];
#pragma unroll 8
                for (int kk = 0; kk < 64; kk++) {
                    float hv = hB[kk * 64 + rr];
                    u64 h2 = bcast2(hv);
                    const float* w = wb + kk * 48;
                    ulonglong2 wz = *(const ulonglong2*)w;
                    ulonglong2 wr = *(const ulonglong2*)(w + 16);
                    fma2(az01, h2, wz.x); fma2(az23, h2, wz.y);
                    fma2(ar01, h2, wr.x); fma2(ar23, h2, wr.y);
                    accd = fmaf(hv, wdb[kk * 4], accd);
                }
                if (c == cjb) {
                    h40 = hB[(jbl + 0) * 64 + rr];
                    h41 = hB[(jbl + 1) * 64 + rr];
                    h42 = hB[(jbl + 2) * 64 + rr];
                    h43 = hB[(jbl + 3) * 64 + rr];
                }
            } else {
                const float* wdb = &WdS[(c * 64) * 4 + tc];
#pragma unroll 8
                for (int kk = 0; kk < 64; kk++)
                    accd = fmaf(hB[kk * 64 + rr], wdb[kk * 4], accd);
            }
        }

        if (t >= 1) {
            __syncthreads();                 // all warps done with last chunk buffer
            dpS[rr * 4 + tc] = accd;
            __syncthreads();
            if (tc < 2) {
                float mu  = dpS[rr * 4 + tc];
                float raw = dpS[rr * 4 + 2 + tc];
                float sp  = fmaxf(raw, 0.0f) + log1pf(__expf(-fabsf(raw)));
                float sig = sp + 1e-4f;
                float lsig = logf(sig);
                int l = cg * 2 + tc;
                float eps = noise[((size_t)tm1 * ROWS + grow) * LL + l];
                float zv  = fmaf(sig, eps, mu);
                d_zT[l * ROWS + grow] = zv;
                out_z[((size_t)grow * T_STEPS + tm1) * LL + l] = zv;
                lsS[rr * 2 + tc] = lsig;
                lpS[rr * 2 + tc] = fmaf(-0.5f * eps, eps, -lsig);
            }
            __syncthreads();
            if (tc == 0) {
                float plsig = lsS[rr * 2] + lsS[rr * 2 + 1];
                float plp   = lpS[rr * 2] + lpS[rr * 2 + 1];
                d_red[(grow * 32 + cg) * 2 + 0] = plsig;
                d_red[(grow * 32 + cg) * 2 + 1] = plp;
            }
        }

        grid_barrier(++gen);

        // =============== P2: ent/lp reduction + z-part gates + rh ==================
        if (t < T_STEPS) {
#pragma unroll
            for (int it = 0; it < 4; it++) {
                int idx4 = tid + it * 256;
                int l = idx4 >> 4, q = idx4 & 15;
                cp16(&zS[l * 64 + q * 4], &d_zT[l * ROWS + rg * 64 + q * 4]);
            }
            CP_COMMIT();
        }

        if (t >= 1) {
            int w = tid >> 5, lane = tid & 31;
            int row = blockIdx.x * 2 + (w >> 2);
            int sel = w & 3;
            if (sel < 2) {
                float v;
                asm volatile("ld.global.cg.f32 %0, [%1];" : "=f"(v)
                             : "l"(&d_red[(row * 32 + lane) * 2 + sel]));
#pragma unroll
                for (int off = 16; off; off >>= 1) v += __shfl_down_sync(0xffffffffu, v, off);
                if (lane == 0) {
                    if (sel == 0)
                        out_ent[(size_t)row * T_STEPS + tm1] = 32.0f * (LOG2PI_F + 1.0f) + v;
                    else
                        out_lp[(size_t)row * T_STEPS + tm1] = v - 32.0f * LOG2PI_F;
                }
            }
        }

        if (t == T_STEPS) break;

        CP_WAIT0();
        __syncthreads();

#pragma unroll 4
        for (int l = 0; l < LL; l++) {
            u64 z2 = bcast2(zS[l * 64 + rr]);
            const float* w = &WxzS[l * 48 + tc * 4];
            ulonglong2 wz = *(const ulonglong2*)(w);
            ulonglong2 wr = *(const ulonglong2*)(w + 16);
            ulonglong2 wn = *(const ulonglong2*)(w + 32);
            fma2(az01, z2, wz.x); fma2(az23, z2, wz.y);
            fma2(ar01, z2, wr.x); fma2(ar23, z2, wr.y);
            fma2(an01, z2, wn.x); fma2(an23, z2, wn.y);
        }
        {
            float az0, az1, az2, az3, ar0, ar1, ar2, ar3;
            unpack2(az01, az0, az1); unpack2(az23, az2, az3);
            unpack2(ar01, ar0, ar1); unpack2(ar23, ar2, ar3);
            zg0 = __fdividef(1.0f, 1.0f + __expf(-az0));
            zg1 = __fdividef(1.0f, 1.0f + __expf(-az1));
            zg2 = __fdividef(1.0f, 1.0f + __expf(-az2));
            zg3 = __fdividef(1.0f, 1.0f + __expf(-az3));
            float rgt0 = __fdividef(1.0f, 1.0f + __expf(-ar0));
            float rgt1 = __fdividef(1.0f, 1.0f + __expf(-ar1));
            float rgt2 = __fdividef(1.0f, 1.0f + __expf(-ar2));
            float rgt3 = __fdividef(1.0f, 1.0f + __expf(-ar3));
            d_rhT[(jb + 0) * ROWS + grow] = rgt0 * h40;
            d_rhT[(jb + 1) * ROWS + grow] = rgt1 * h41;
            d_rhT[(jb + 2) * ROWS + grow] = rgt2 * h42;
            d_rhT[(jb + 3) * ROWS + grow] = rgt3 * h43;
        }

        grid_barrier(++gen);

        // =============== P3: rh-GEMM (n) + blend + h write =========================
#pragma unroll
        for (int pre = 0; pre < 2; pre++) {
#pragma unroll
            for (int it = 0; it < 4; it++) {
                int idx4 = tid + it * 256;
                int kk = idx4 >> 4, q = idx4 & 15;
                cp16(&sm[SM_H + pre * 4096 + kk * 64 + q * 4],
                     &d_rhT[(pre * 64 + kk) * ROWS + rg * 64 + q * 4]);
            }
            CP_COMMIT();
        }

        for (int c = 0; c < 8; c++) {
            if (c + 2 < 8) {
                int cs = c + 2;
#pragma unroll
                for (int it = 0; it < 4; it++) {
                    int idx4 = tid + it * 256;
                    int kk = idx4 >> 4, q = idx4 & 15;
                    cp16(&sm[SM_H + (cs & 3) * 4096 + kk * 64 + q * 4],
                         &d_rhT[(cs * 64 + kk) * ROWS + rg * 64 + q * 4]);
                }
            }
            CP_COMMIT();
            CP_WAIT2();
            __syncthreads();

            const float* hB = sm + SM_H + (c & 3) * 4096;
            const float* wb = &WhS[(c * 64) * 48 + 32 + tc * 4];
#pragma unroll 8
            for (int kk = 0; kk < 64; kk++) {
                u64 r2 = bcast2(hB[kk * 64 + rr]);
                ulonglong2 wn = *(const ulonglong2*)(wb + kk * 48);
                fma2(an01, r2, wn.x); fma2(an23, r2, wn.y);
            }
        }

        {
            float an0, an1, an2, an3;
            unpack2(an01, an0, an1); unpack2(an23, an2, an3);
            float n0 = tanhf(an0), n1 = tanhf(an1), n2 = tanhf(an2), n3 = tanhf(an3);
            d_hT[(jb + 0) * ROWS + grow] = (1.0f - zg0) * n0 + zg0 * h40;
            d_hT[(jb + 1) * ROWS + grow] = (1.0f - zg1) * n1 + zg1 * h41;
            d_hT[(jb + 2) * ROWS + grow] = (1.0f - zg2) * n2 + zg2 * h42;
            d_hT[(jb + 3) * ROWS + grow] = (1.0f - zg3) * n3 + zg3 * h43;
        }

        // ---- prefetch XG for next step (hides its L2 latency behind the barrier) --
        if (t + 1 < T_STEPS) {
            const float* xg_t = d_XG + (size_t)(t + 1) * BB * NC3;
#pragma unroll
            for (int it = 0; it < 3; it++) {
                int idx4 = tid + it * 256;
                int b = idx4 / 12, uu = idx4 % 12;
                cp16(&XGS[b * 48 + uu * 4],
                     &xg_t[(size_t)b * NC3 + (uu >> 2) * HH + cg * 16 + (uu & 3) * 4]);
            }
            CP_COMMIT();
        }

        grid_barrier(++gen);
    }
}

// ---------------- launch ---------------------------------------------------------
extern "C" void kernel_launch(void* const* d_in, const int* in_sizes, int n_in,
                              void* d_out, int out_size) {
    const float* inp   = (const float*)d_in[0];   // (B,T,D)
    const float* noise = (const float*)d_in[1];   // (T,S*B,L)
    const float* Wx    = (const float*)d_in[2];   // (D+L,3H)
    const float* Wh    = (const float*)d_in[3];   // (H,3H)
    const float* bias  = (const float*)d_in[4];   // (3H,)
    const float* Wd    = (const float*)d_in[5];   // (H,2L)
    const float* bd    = (const float*)d_in[6];   // (2L,)
    float* out = (float*)d_out;

    cudaFuncSetAttribute(scan_kernel, cudaFuncAttributeMaxDynamicSharedMemorySize, SMEM_BYTES);

    init_a<<<32, 256>>>();
    init_b<<<32, 256>>>();
    init_c<<<16, 256>>>();
    init_d<<<32, 256>>>();

    dim3 gA(NC3 / ABN, (T_STEPS * BB) / ABM);     // 24 x 1024
    xg_kernel<<<gA, 256>>>(inp, Wx, bias);

    scan_kernel<<<NCTA, BLK, SMEM_BYTES>>>(noise, Wx, Wh, Wd, bd, out);
}